// round 16
// baseline (speedup 1.0000x reference)
#include <cuda_runtime.h>
#include <cuda_fp16.h>
#include <cstdint>

#define N_NODES 50000
#define E_MAX   800000
#define D 128
#define D_OUT 64
#define BN_EPS 1e-5f
#define WTOT (2 * 128 * 256 + 128 * 128)

// ---------------- scratch (device globals; no allocation allowed) ----------
__device__ __half g_xh[(size_t)N_NODES * D];   // fp16 copy of x
__device__ __half g_M[(size_t)N_NODES * D];    // neighbor mean (fp16)
__device__ __half g_W[WTOT];                   // fp16 weights (all layers, transposed)
__device__ __half g_h0[(size_t)N_NODES * D];   // layer0 out; later reused for [z2|s2]
__device__ __half g_h1[(size_t)N_NODES * D];
__device__ int    g_cnti[N_NODES];
__device__ int    g_rowptr[N_NODES + 1];
__device__ int    g_rank[E_MAX];
__device__ int    g_csr[E_MAX];
__device__ float  g_sum0[D];
__device__ float  g_sq0[D];
__device__ float  g_sum1[D];
__device__ float  g_sq1[D];

// ---------------- helpers ----------------------------------------------------
__device__ __forceinline__ uint32_t smem_u32(const void* p) {
    return (uint32_t)__cvta_generic_to_shared(p);
}

__device__ __forceinline__ void ldsm4(uint32_t* r, uint32_t a) {
    asm volatile("ldmatrix.sync.aligned.m8n8.x4.shared.b16 {%0,%1,%2,%3}, [%4];"
                 : "=r"(r[0]), "=r"(r[1]), "=r"(r[2]), "=r"(r[3]) : "r"(a));
}

__device__ __forceinline__ void mma16816f(float* d, const uint32_t* a, const uint32_t* b) {
    asm volatile("mma.sync.aligned.m16n8k16.row.col.f32.f16.f16.f32 "
                 "{%0,%1,%2,%3}, {%4,%5,%6,%7}, {%8,%9}, {%0,%1,%2,%3};"
                 : "+f"(d[0]), "+f"(d[1]), "+f"(d[2]), "+f"(d[3])
                 : "r"(a[0]), "r"(a[1]), "r"(a[2]), "r"(a[3]), "r"(b[0]), "r"(b[1]));
}

__device__ __forceinline__ void cp_async16(uint32_t sa, const void* g, int sz) {
    asm volatile("cp.async.cg.shared.global [%0], [%1], 16, %2;"
                 :: "r"(sa), "l"(g), "r"(sz) : "memory");
}
__device__ __forceinline__ void cp_commit() {
    asm volatile("cp.async.commit_group;" ::: "memory");
}
__device__ __forceinline__ void cp_wait0() {
    asm volatile("cp.async.wait_group 0;" ::: "memory");
}

// ---------------- prep A: degree histogram + ranks (critical path) ----------
__global__ void k_prep_graph(const int* __restrict__ dst, int E,
                             int* __restrict__ cnt, int* __restrict__ rank) {
    int idx = blockIdx.x * blockDim.x + threadIdx.x;
    int stride = gridDim.x * blockDim.x;
    int nQ = E >> 2;
    for (int q = idx; q < nQ; q += stride) {
        int4 d = __ldg(reinterpret_cast<const int4*>(dst) + q);
        int4 r;
        r.x = atomicAdd(&cnt[d.x], 1);
        r.y = atomicAdd(&cnt[d.y], 1);
        r.z = atomicAdd(&cnt[d.z], 1);
        r.w = atomicAdd(&cnt[d.w], 1);
        *(reinterpret_cast<int4*>(rank) + q) = r;
    }
    for (int e = nQ * 4 + idx; e < E; e += stride)
        rank[e] = atomicAdd(&cnt[__ldg(dst + e)], 1);
}

// ---------------- prep B: weights->fp16 + x->fp16 (off critical path) -------
__global__ void k_prep_data(const float* __restrict__ x, __half* __restrict__ xh,
                            const float* __restrict__ Wl0, const float* __restrict__ Wr0,
                            const float* __restrict__ Wl1, const float* __restrict__ Wr1,
                            const float* __restrict__ Wl2, const float* __restrict__ Wr2,
                            __half* __restrict__ W) {
    int idx = blockIdx.x * blockDim.x + threadIdx.x;
    int stride = gridDim.x * blockDim.x;

    if (idx < WTOT) {
        const int T01 = 128 * 256;
        float v;
        if (idx < T01) {
            int n = idx >> 8, k = idx & 255;
            v = (k < 128) ? __ldg(Wl0 + k * 128 + n) : __ldg(Wr0 + (k - 128) * 128 + n);
        } else if (idx < 2 * T01) {
            int l = idx - T01;
            int n = l >> 8, k = l & 255;
            v = (k < 128) ? __ldg(Wl1 + k * 128 + n) : __ldg(Wr1 + (k - 128) * 128 + n);
        } else {
            int l = idx - 2 * T01;
            int n = l >> 7, k = l & 127;
            v = (n < 64) ? __ldg(Wl2 + k * 64 + n) : __ldg(Wr2 + k * 64 + (n - 64));
        }
        W[idx] = __float2half_rn(v);
    }

    const int X8 = N_NODES * D / 8;
    for (int i = idx; i < X8; i += stride) {
        float4 u0 = __ldg(reinterpret_cast<const float4*>(x) + i * 2);
        float4 u1 = __ldg(reinterpret_cast<const float4*>(x) + i * 2 + 1);
        __half2 h[4];
        h[0] = __float22half2_rn(make_float2(u0.x, u0.y));
        h[1] = __float22half2_rn(make_float2(u0.z, u0.w));
        h[2] = __float22half2_rn(make_float2(u1.x, u1.y));
        h[3] = __float22half2_rn(make_float2(u1.z, u1.w));
        reinterpret_cast<uint4*>(xh)[i] = *reinterpret_cast<uint4*>(h);
    }
}

// single block, 1024 threads: chunked warp-shuffle exclusive scan.
// Coalesced loads; self-zeroes cnt for next graph replay.
__global__ void k_scan(int* __restrict__ cnt, int* __restrict__ row_ptr) {
    __shared__ int warpsum[32];
    __shared__ int carry;
    const int t = threadIdx.x;
    const int lane = t & 31;
    const int wid = t >> 5;
    if (t == 0) carry = 0;
    __syncthreads();

    const int NCH = (N_NODES + 1023) / 1024;
    for (int ch = 0; ch < NCH; ch++) {
        int i = ch * 1024 + t;
        int v = 0;
        if (i < N_NODES) { v = cnt[i]; cnt[i] = 0; }
        int s = v;
#pragma unroll
        for (int o = 1; o < 32; o <<= 1) {
            int u = __shfl_up_sync(0xffffffffu, s, o);
            if (lane >= o) s += u;
        }
        if (lane == 31) warpsum[wid] = s;
        __syncthreads();
        if (wid == 0) {
            int ws = warpsum[lane];
#pragma unroll
            for (int o = 1; o < 32; o <<= 1) {
                int u = __shfl_up_sync(0xffffffffu, ws, o);
                if (lane >= o) ws += u;
            }
            warpsum[lane] = ws;
        }
        __syncthreads();
        int wbase = (wid > 0) ? warpsum[wid - 1] : 0;
        int base = carry;
        if (i < N_NODES) row_ptr[i] = base + wbase + s - v;
        __syncthreads();
        if (t == 0) carry += warpsum[31];
        __syncthreads();
    }
    if (t == 0) row_ptr[N_NODES] = carry;
}

// atomic-free fill using precomputed ranks
__global__ void k_fill(const int* __restrict__ src, const int* __restrict__ dst,
                       int E, const int* __restrict__ rank,
                       const int* __restrict__ row_ptr, int* __restrict__ csr) {
    int i = blockIdx.x * blockDim.x + threadIdx.x;
    int stride = gridDim.x * blockDim.x;
    int nQ = E >> 2;
    for (int q = i; q < nQ; q += stride) {
        int4 d = __ldg(reinterpret_cast<const int4*>(dst) + q);
        int4 s = __ldg(reinterpret_cast<const int4*>(src) + q);
        int4 r = __ldg(reinterpret_cast<const int4*>(rank) + q);
        csr[__ldg(row_ptr + d.x) + r.x] = s.x;
        csr[__ldg(row_ptr + d.y) + r.y] = s.y;
        csr[__ldg(row_ptr + d.z) + r.z] = s.z;
        csr[__ldg(row_ptr + d.w) + r.w] = s.w;
    }
    for (int e = nQ * 4 + i; e < E; e += stride)
        csr[__ldg(row_ptr + __ldg(dst + e)) + __ldg(rank + e)] = __ldg(src + e);
}

// ---------------- aggregation: fp16 gather, 4-edge fp16 tree reduction ------
// One warp per node; block 0 zeroes the given stats buffers.
__global__ __launch_bounds__(256)
void k_aggregate(const __half* __restrict__ xin, const int* __restrict__ csr,
                 const int* __restrict__ row_ptr, __half* __restrict__ M,
                 float* __restrict__ zSum, float* __restrict__ zSq) {
    int tid = threadIdx.x;
    if (blockIdx.x == 0 && tid < 128) { zSum[tid] = 0.f; zSq[tid] = 0.f; }

    int w = (blockIdx.x * blockDim.x + tid) >> 5;
    if (w >= N_NODES) return;
    int lane = tid & 31;

    int beg = __ldg(row_ptr + w);
    int end = __ldg(row_ptr + w + 1);
    float4 acc = make_float4(0.f, 0.f, 0.f, 0.f);

    int i = beg;
    for (; i + 3 < end; i += 4) {
        int s0 = __ldg(csr + i);
        int s1 = __ldg(csr + i + 1);
        int s2 = __ldg(csr + i + 2);
        int s3 = __ldg(csr + i + 3);
        uint2 u0 = __ldg(reinterpret_cast<const uint2*>(xin + (size_t)s0 * D) + lane);
        uint2 u1 = __ldg(reinterpret_cast<const uint2*>(xin + (size_t)s1 * D) + lane);
        uint2 u2 = __ldg(reinterpret_cast<const uint2*>(xin + (size_t)s2 * D) + lane);
        uint2 u3 = __ldg(reinterpret_cast<const uint2*>(xin + (size_t)s3 * D) + lane);
        __half2 a_lo = __hadd2(*reinterpret_cast<__half2*>(&u0.x), *reinterpret_cast<__half2*>(&u1.x));
        __half2 a_hi = __hadd2(*reinterpret_cast<__half2*>(&u0.y), *reinterpret_cast<__half2*>(&u1.y));
        __half2 b_lo = __hadd2(*reinterpret_cast<__half2*>(&u2.x), *reinterpret_cast<__half2*>(&u3.x));
        __half2 b_hi = __hadd2(*reinterpret_cast<__half2*>(&u2.y), *reinterpret_cast<__half2*>(&u3.y));
        __half2 t_lo = __hadd2(a_lo, b_lo);
        __half2 t_hi = __hadd2(a_hi, b_hi);
        float2 f0 = __half22float2(t_lo);
        float2 f1 = __half22float2(t_hi);
        acc.x += f0.x; acc.y += f0.y; acc.z += f1.x; acc.w += f1.y;
    }
    for (; i < end; i++) {
        int s0 = __ldg(csr + i);
        uint2 u0 = __ldg(reinterpret_cast<const uint2*>(xin + (size_t)s0 * D) + lane);
        float2 f0 = __half22float2(*reinterpret_cast<__half2*>(&u0.x));
        float2 f1 = __half22float2(*reinterpret_cast<__half2*>(&u0.y));
        acc.x += f0.x; acc.y += f0.y; acc.z += f1.x; acc.w += f1.y;
    }

    float inv = 1.f / (float)max(end - beg, 1);
    __half2 o[2];
    o[0] = __float22half2_rn(make_float2(acc.x * inv, acc.y * inv));
    o[1] = __float22half2_rn(make_float2(acc.z * inv, acc.w * inv));
    *reinterpret_cast<uint2*>(M + (size_t)w * D + lane * 4) = *reinterpret_cast<uint2*>(o);
}

// ---------------- BN+ReLU in place on fp16 h (layer 0 only) -----------------
__global__ __launch_bounds__(256)
void k_bn_apply(__half* __restrict__ h,
                const float* __restrict__ stSum, const float* __restrict__ stSq,
                const float* __restrict__ gamma, const float* __restrict__ beta) {
    __shared__ float ssc[128], ssh[128];
    int tid = threadIdx.x;
    if (tid < 128) {
        float mu = __ldg(stSum + tid) / (float)N_NODES;
        float var = __ldg(stSq + tid) / (float)N_NODES - mu * mu;
        float sc = __ldg(gamma + tid) * rsqrtf(var + BN_EPS);
        ssc[tid] = sc;
        ssh[tid] = __ldg(beta + tid) - mu * sc;
    }
    __syncthreads();

    const int T8 = N_NODES * D / 8;
    for (int i = blockIdx.x * blockDim.x + tid; i < T8; i += gridDim.x * blockDim.x) {
        int c8 = (i & 15) * 8;
        uint4 u = *(reinterpret_cast<uint4*>(h) + i);
        __half2* hp = reinterpret_cast<__half2*>(&u);
#pragma unroll
        for (int j = 0; j < 4; j++) {
            float2 f = __half22float2(hp[j]);
            f.x = fmaxf(fmaf(f.x, ssc[c8 + 2 * j], ssh[c8 + 2 * j]), 0.f);
            f.y = fmaxf(fmaf(f.y, ssc[c8 + 2 * j + 1], ssh[c8 + 2 * j + 1]), 0.f);
            hp[j] = __float22half2_rn(f);
        }
        *(reinterpret_cast<uint4*>(h) + i) = u;
    }
}

// ---------------- fp16 HMMA GEMM layers 0/1 (K=256, N=128), cp.async 2-buf --
__global__ __launch_bounds__(256)
void k_mma_gemm(const __half* __restrict__ M, const __half* __restrict__ selfSrc,
                const __half* __restrict__ W, const float* __restrict__ bias,
                __half* __restrict__ out,
                float* __restrict__ stOutSum, float* __restrict__ stOutSq) {
    constexpr int RS = 72;
    constexpr int NT = 8;
    constexpr int BUF = 128 * RS;
    extern __shared__ __half sm[];

    __shared__ float ssum[128];
    __shared__ float ssq[128];

    const int tid = threadIdx.x;
    const int lane = tid & 31;
    const int warp = tid >> 5;
    const int wr = warp & 3;
    const int wc = warp >> 2;
    const int rowBase = blockIdx.x * 128;

    if (tid < 128) { ssum[tid] = 0.f; ssq[tid] = 0.f; }

    float acc[2][NT][4];
#pragma unroll
    for (int mt = 0; mt < 2; mt++)
#pragma unroll
        for (int nt = 0; nt < NT; nt++)
#pragma unroll
            for (int j = 0; j < 4; j++) acc[mt][nt][j] = 0.f;

    auto issue = [&](int stage, int b) {
        const __half* Asrc = (stage < 2) ? M : selfSrc;
        const int colBase = (stage & 1) * 64;
        __half* sA = sm + b * 2 * BUF;
        __half* sW = sA + BUF;
#pragma unroll
        for (int t = 0; t < 4; t++) {
            int idx = tid + t * 256;
            int r = idx >> 3, c = idx & 7;
            int row = rowBase + r;
            int ok = (row < N_NODES) ? 16 : 0;
            int srow = (row < N_NODES) ? row : 0;
            cp_async16(smem_u32(sA + r * RS + c * 8),
                       Asrc + (size_t)srow * D + colBase + c * 8, ok);
        }
#pragma unroll
        for (int t = 0; t < 4; t++) {
            int idx = tid + t * 256;
            int n = idx >> 3, c = idx & 7;
            cp_async16(smem_u32(sW + n * RS + c * 8),
                       W + (size_t)n * 256 + stage * 64 + c * 8, 16);
        }
        cp_commit();
    };

    issue(0, 0);

    for (int stage = 0; stage < 4; stage++) {
        cp_wait0();
        __syncthreads();
        if (stage + 1 < 4) issue(stage + 1, (stage + 1) & 1);

        const uint32_t sbA = smem_u32(sm + (stage & 1) * 2 * BUF);
        const uint32_t sbW = sbA + BUF * 2;

#pragma unroll
        for (int ks = 0; ks < 4; ks++) {
            const uint32_t koff = (uint32_t)(ks * 16 + (lane >> 4) * 8) * 2;
            uint32_t a[2][4];
#pragma unroll
            for (int mt = 0; mt < 2; mt++) {
                uint32_t roff = (uint32_t)(wr * 32 + mt * 16 + (lane & 15)) * (RS * 2) + koff;
                ldsm4(a[mt], sbA + roff);
            }
            uint32_t b[NT][2];
#pragma unroll
            for (int g = 0; g < NT / 2; g++) {
                uint32_t roff = (uint32_t)(wc * 64 + g * 16 + (lane & 15)) * (RS * 2) + koff;
                uint32_t r[4];
                ldsm4(r, sbW + roff);
                b[2 * g][0] = r[0]; b[2 * g][1] = r[2];
                b[2 * g + 1][0] = r[1]; b[2 * g + 1][1] = r[3];
            }
#pragma unroll
            for (int mt = 0; mt < 2; mt++)
#pragma unroll
                for (int nt = 0; nt < NT; nt++)
                    mma16816f(acc[mt][nt], a[mt], b[nt]);
        }
        __syncthreads();
    }

#pragma unroll
    for (int nt = 0; nt < NT; nt++) {
        int col = wc * 64 + nt * 8 + (lane & 3) * 2;
        float2 bb = *reinterpret_cast<const float2*>(bias + col);
        float s0 = 0.f, s1 = 0.f, q0 = 0.f, q1 = 0.f;
#pragma unroll
        for (int mt = 0; mt < 2; mt++) {
            int r0 = rowBase + wr * 32 + mt * 16 + (lane >> 2);
            float v0 = acc[mt][nt][0] + bb.x, v1 = acc[mt][nt][1] + bb.y;
            float v2 = acc[mt][nt][2] + bb.x, v3 = acc[mt][nt][3] + bb.y;
            if (r0 < N_NODES) {
                *reinterpret_cast<__half2*>(out + (size_t)r0 * 128 + col) =
                    __float22half2_rn(make_float2(v0, v1));
                s0 += v0; s1 += v1; q0 += v0 * v0; q1 += v1 * v1;
            }
            if (r0 + 8 < N_NODES) {
                *reinterpret_cast<__half2*>(out + (size_t)(r0 + 8) * 128 + col) =
                    __float22half2_rn(make_float2(v2, v3));
                s0 += v2; s1 += v3; q0 += v2 * v2; q1 += v3 * v3;
            }
        }
#pragma unroll
        for (int off = 4; off < 32; off <<= 1) {
            s0 += __shfl_down_sync(0xffffffffu, s0, off);
            s1 += __shfl_down_sync(0xffffffffu, s1, off);
            q0 += __shfl_down_sync(0xffffffffu, q0, off);
            q1 += __shfl_down_sync(0xffffffffu, q1, off);
        }
        if ((lane >> 2) == 0) {
            atomicAdd(&ssum[col], s0); atomicAdd(&ssum[col + 1], s1);
            atomicAdd(&ssq[col], q0);  atomicAdd(&ssq[col + 1], q1);
        }
    }
    __syncthreads();
    if (tid < 128) {
        atomicAdd(&stOutSum[tid], ssum[tid]);
        atomicAdd(&stOutSq[tid], ssq[tid]);
    }
}

// ---------------- layer-2 GEMM: [z | s+b2] = relu(bn(h1)) @ [Wl2|Wr2]^T -----
__global__ __launch_bounds__(256)
void k_gemm_l2(const __half* __restrict__ hin,
               const float* __restrict__ stSum, const float* __restrict__ stSq,
               const float* __restrict__ gamma, const float* __restrict__ beta,
               const __half* __restrict__ W, const float* __restrict__ b2,
               __half* __restrict__ zout) {
    constexpr int RS = 72;
    constexpr int NT = 8;
    extern __shared__ __half sm[];
    __half* sA = sm;
    __half* sW = sm + 128 * RS;

    __shared__ float ssc[128], ssh[128];

    const int tid = threadIdx.x;
    const int lane = tid & 31;
    const int warp = tid >> 5;
    const int wr = warp & 3;
    const int wc = warp >> 2;
    const int rowBase = blockIdx.x * 128;

    if (tid < 128) {
        float mu = __ldg(stSum + tid) / (float)N_NODES;
        float var = __ldg(stSq + tid) / (float)N_NODES - mu * mu;
        float sc = __ldg(gamma + tid) * rsqrtf(var + BN_EPS);
        ssc[tid] = sc;
        ssh[tid] = __ldg(beta + tid) - mu * sc;
    }
    __syncthreads();

    const uint32_t sbA = smem_u32(sA);
    const uint32_t sbW = smem_u32(sW);

    float acc[2][NT][4];
#pragma unroll
    for (int mt = 0; mt < 2; mt++)
#pragma unroll
        for (int nt = 0; nt < NT; nt++)
#pragma unroll
            for (int j = 0; j < 4; j++) acc[mt][nt][j] = 0.f;

    for (int stage = 0; stage < 2; stage++) {
#pragma unroll
        for (int t = 0; t < 4; t++) {
            int idx = tid + t * 256;
            int r = idx >> 3, c = idx & 7;
            int row = rowBase + r;
            int col0 = stage * 64 + c * 8;
            uint4 u = make_uint4(0, 0, 0, 0);
            if (row < N_NODES) {
                u = __ldg(reinterpret_cast<const uint4*>(hin + (size_t)row * D + col0));
                __half2* hp = reinterpret_cast<__half2*>(&u);
#pragma unroll
                for (int j = 0; j < 4; j++) {
                    float2 f = __half22float2(hp[j]);
                    f.x = fmaxf(fmaf(f.x, ssc[col0 + 2 * j], ssh[col0 + 2 * j]), 0.f);
                    f.y = fmaxf(fmaf(f.y, ssc[col0 + 2 * j + 1], ssh[col0 + 2 * j + 1]), 0.f);
                    hp[j] = __float22half2_rn(f);
                }
            }
            *reinterpret_cast<uint4*>(sA + r * RS + c * 8) = u;
        }
#pragma unroll
        for (int t = 0; t < 4; t++) {
            int idx = tid + t * 256;
            int n = idx >> 3, c = idx & 7;
            uint4 v = __ldg(reinterpret_cast<const uint4*>(W + (size_t)n * 128 + stage * 64) + c);
            *reinterpret_cast<uint4*>(sW + n * RS + c * 8) = v;
        }
        __syncthreads();

#pragma unroll
        for (int ks = 0; ks < 4; ks++) {
            const uint32_t koff = (uint32_t)(ks * 16 + (lane >> 4) * 8) * 2;
            uint32_t a[2][4];
#pragma unroll
            for (int mt = 0; mt < 2; mt++) {
                uint32_t roff = (uint32_t)(wr * 32 + mt * 16 + (lane & 15)) * (RS * 2) + koff;
                ldsm4(a[mt], sbA + roff);
            }
            uint32_t b[NT][2];
#pragma unroll
            for (int g = 0; g < NT / 2; g++) {
                uint32_t roff = (uint32_t)(wc * 64 + g * 16 + (lane & 15)) * (RS * 2) + koff;
                uint32_t r[4];
                ldsm4(r, sbW + roff);
                b[2 * g][0] = r[0]; b[2 * g][1] = r[2];
                b[2 * g + 1][0] = r[1]; b[2 * g + 1][1] = r[3];
            }
#pragma unroll
            for (int mt = 0; mt < 2; mt++)
#pragma unroll
                for (int nt = 0; nt < NT; nt++)
                    mma16816f(acc[mt][nt], a[mt], b[nt]);
        }
        __syncthreads();
    }

#pragma unroll
    for (int nt = 0; nt < NT; nt++) {
        int col = wc * 64 + nt * 8 + (lane & 3) * 2;
        float2 bb = make_float2(0.f, 0.f);
        if (wc == 1) bb = *reinterpret_cast<const float2*>(b2 + (col - 64));
#pragma unroll
        for (int mt = 0; mt < 2; mt++) {
            int r0 = rowBase + wr * 32 + mt * 16 + (lane >> 2);
            if (r0 < N_NODES)
                *reinterpret_cast<__half2*>(zout + (size_t)r0 * 128 + col) =
                    __float22half2_rn(make_float2(acc[mt][nt][0] + bb.x, acc[mt][nt][1] + bb.y));
            if (r0 + 8 < N_NODES)
                *reinterpret_cast<__half2*>(zout + (size_t)(r0 + 8) * 128 + col) =
                    __float22half2_rn(make_float2(acc[mt][nt][2] + bb.x, acc[mt][nt][3] + bb.y));
        }
    }
}

// ---------------- final: out = log_softmax(mean(z[src]) + (s+b2)) -----------
__global__ __launch_bounds__(256)
void k_final(const __half* __restrict__ zs, const int* __restrict__ csr,
             const int* __restrict__ row_ptr, float* __restrict__ out) {
    int w = (blockIdx.x * blockDim.x + threadIdx.x) >> 5;
    if (w >= N_NODES) return;
    int lane = threadIdx.x & 31;
    int beg = __ldg(row_ptr + w);
    int end = __ldg(row_ptr + w + 1);
    float2 a = make_float2(0.f, 0.f);
    int i = beg;
    for (; i + 3 < end; i += 4) {
        int s0 = __ldg(csr + i);
        int s1 = __ldg(csr + i + 1);
        int s2 = __ldg(csr + i + 2);
        int s3 = __ldg(csr + i + 3);
        __half2 u0 = __ldg(reinterpret_cast<const __half2*>(zs + (size_t)s0 * 128) + lane);
        __half2 u1 = __ldg(reinterpret_cast<const __half2*>(zs + (size_t)s1 * 128) + lane);
        __half2 u2 = __ldg(reinterpret_cast<const __half2*>(zs + (size_t)s2 * 128) + lane);
        __half2 u3 = __ldg(reinterpret_cast<const __half2*>(zs + (size_t)s3 * 128) + lane);
        __half2 t = __hadd2(__hadd2(u0, u1), __hadd2(u2, u3));
        float2 f = __half22float2(t);
        a.x += f.x; a.y += f.y;
    }
    for (; i < end; i++) {
        int s0 = __ldg(csr + i);
        float2 f = __half22float2(__ldg(reinterpret_cast<const __half2*>(zs + (size_t)s0 * 128) + lane));
        a.x += f.x; a.y += f.y;
    }
    float inv = 1.f / (float)max(end - beg, 1);
    float2 sv = __half22float2(__ldg(reinterpret_cast<const __half2*>(zs + (size_t)w * 128 + 64) + lane));
    float v0 = a.x * inv + sv.x;
    float v1 = a.y * inv + sv.y;
    float m = fmaxf(v0, v1);
#pragma unroll
    for (int o = 16; o > 0; o >>= 1) m = fmaxf(m, __shfl_xor_sync(0xffffffffu, m, o));
    float e = expf(v0 - m) + expf(v1 - m);
#pragma unroll
    for (int o = 16; o > 0; o >>= 1) e += __shfl_xor_sync(0xffffffffu, e, o);
    float l = m + logf(e);
    *(reinterpret_cast<float2*>(out + (size_t)w * D_OUT) + lane) = make_float2(v0 - l, v1 - l);
}

// ---------------- launch ----------------------------------------------------
extern "C" void kernel_launch(void* const* d_in, const int* in_sizes, int n_in,
                              void* d_out, int out_size) {
    const float* x   = (const float*)d_in[0];
    const int* ei    = (const int*)d_in[1];
    const float* Wl0 = (const float*)d_in[2];
    const float* Wr0 = (const float*)d_in[3];
    const float* b0  = (const float*)d_in[4];
    const float* g0  = (const float*)d_in[5];
    const float* be0 = (const float*)d_in[6];
    const float* Wl1 = (const float*)d_in[7];
    const float* Wr1 = (const float*)d_in[8];
    const float* b1  = (const float*)d_in[9];
    const float* g1  = (const float*)d_in[10];
    const float* be1 = (const float*)d_in[11];
    const float* Wl2 = (const float*)d_in[12];
    const float* Wr2 = (const float*)d_in[13];
    const float* b2  = (const float*)d_in[14];
    float* out = (float*)d_out;

    const int E = in_sizes[1] / 2;
    const int* src = ei;
    const int* dst = ei + E;

    __half *xh, *M, *W, *h0, *h1;
    float *sum0, *sq0, *sum1, *sq1;
    int *cnti, *rowptr, *rank, *csr;
    cudaGetSymbolAddress((void**)&xh, g_xh);
    cudaGetSymbolAddress((void**)&M, g_M);
    cudaGetSymbolAddress((void**)&W, g_W);
    cudaGetSymbolAddress((void**)&h0, g_h0);
    cudaGetSymbolAddress((void**)&h1, g_h1);
    cudaGetSymbolAddress((void**)&cnti, g_cnti);
    cudaGetSymbolAddress((void**)&rowptr, g_rowptr);
    cudaGetSymbolAddress((void**)&rank, g_rank);
    cudaGetSymbolAddress((void**)&csr, g_csr);
    cudaGetSymbolAddress((void**)&sum0, g_sum0);
    cudaGetSymbolAddress((void**)&sq0, g_sq0);
    cudaGetSymbolAddress((void**)&sum1, g_sum1);
    cudaGetSymbolAddress((void**)&sq1, g_sq1);

    // one-time host resources (streams/events are host objects, not device mem)
    static cudaStream_t sSide = nullptr;
    static cudaEvent_t evFork = nullptr, evJoin = nullptr;
    if (!sSide) {
        cudaStreamCreateWithFlags(&sSide, cudaStreamNonBlocking);
        cudaEventCreateWithFlags(&evFork, cudaEventDisableTiming);
        cudaEventCreateWithFlags(&evJoin, cudaEventDisableTiming);
    }

    constexpr int RS = 72;
    const int SMEM  = 4 * 128 * RS * 2;  // 73728: 2 buffers x (A + W)
    const int SMEM2 = 2 * 128 * RS * 2;  // 36864: single buffer (gemm_l2)
    cudaFuncSetAttribute((const void*)k_mma_gemm, cudaFuncAttributeMaxDynamicSharedMemorySize, SMEM);
    cudaFuncSetAttribute((const void*)k_gemm_l2, cudaFuncAttributeMaxDynamicSharedMemorySize, SMEM2);

    const int aggBlocks  = (N_NODES * 32 + 255) / 256;
    const int gemmBlocks = (N_NODES + 127) / 128;

    __half* W0 = W;
    __half* W1 = W + 128 * 256;
    __half* W2 = W + 256 * 256;

    // ---- prep: fork data conversion onto side stream; CSR build on main ----
    cudaEventRecord(evFork, 0);
    cudaStreamWaitEvent(sSide, evFork, 0);
    k_prep_data<<<1024, 256, 0, sSide>>>(x, xh, Wl0, Wr0, Wl1, Wr1, Wl2, Wr2, W);
    cudaEventRecord(evJoin, sSide);

    k_prep_graph<<<1024, 256>>>(dst, E, cnti, rank);
    k_scan<<<1, 1024>>>(cnti, rowptr);
    k_fill<<<1024, 256>>>(src, dst, E, rank, rowptr, csr);
    cudaStreamWaitEvent(0, evJoin, 0);   // join: agg0/gemm0 need xh + W

    // ---- layer 0 ----
    k_aggregate<<<aggBlocks, 256>>>(xh, csr, rowptr, M, sum0, sq0);
    k_mma_gemm<<<gemmBlocks, 256, SMEM>>>(M, xh, W0, b0, h0, sum0, sq0);
    k_bn_apply<<<1024, 256>>>(h0, sum0, sq0, g0, be0);

    // ---- layer 1 ----
    k_aggregate<<<aggBlocks, 256>>>(h0, csr, rowptr, M, sum1, sq1);
    k_mma_gemm<<<gemmBlocks, 256, SMEM>>>(M, h0, W1, b1, h1, sum1, sq1);

    // ---- layer 2 (BN1 fused into GEMM A-load; then fp16 gather + softmax) --
    k_gemm_l2<<<gemmBlocks, 256, SMEM2>>>(h1, sum1, sq1, g1, be1, W2, b2, h0);
    k_final<<<aggBlocks, 256>>>(h0, csr, rowptr, out);
}

// round 17
// speedup vs baseline: 1.0025x; 1.0025x over previous
#include <cuda_runtime.h>
#include <cuda_fp16.h>
#include <cstdint>

#define N_NODES 50000
#define E_MAX   800000
#define D 128
#define D_OUT 64
#define BN_EPS 1e-5f
#define WTOT (2 * 128 * 256 + 128 * 128)

// ---------------- scratch (device globals; no allocation allowed) ----------
__device__ __half g_xh[(size_t)N_NODES * D];   // fp16 copy of x
__device__ __half g_M[(size_t)N_NODES * D];    // neighbor mean (fp16)
__device__ __half g_W[WTOT];                   // fp16 weights (all layers, transposed)
__device__ __half g_h0[(size_t)N_NODES * D];   // layer0 out; later reused for [z2|s2]
__device__ __half g_h1[(size_t)N_NODES * D];
__device__ int    g_cnti[N_NODES];
__device__ int    g_rowptr[N_NODES + 1];
__device__ int    g_rank[E_MAX];
__device__ int    g_csr[E_MAX];
__device__ float  g_sum0[D];
__device__ float  g_sq0[D];
__device__ float  g_sum1[D];
__device__ float  g_sq1[D];

// ---------------- helpers ----------------------------------------------------
__device__ __forceinline__ uint32_t smem_u32(const void* p) {
    return (uint32_t)__cvta_generic_to_shared(p);
}

__device__ __forceinline__ void ldsm4(uint32_t* r, uint32_t a) {
    asm volatile("ldmatrix.sync.aligned.m8n8.x4.shared.b16 {%0,%1,%2,%3}, [%4];"
                 : "=r"(r[0]), "=r"(r[1]), "=r"(r[2]), "=r"(r[3]) : "r"(a));
}

__device__ __forceinline__ void mma16816f(float* d, const uint32_t* a, const uint32_t* b) {
    asm volatile("mma.sync.aligned.m16n8k16.row.col.f32.f16.f16.f32 "
                 "{%0,%1,%2,%3}, {%4,%5,%6,%7}, {%8,%9}, {%0,%1,%2,%3};"
                 : "+f"(d[0]), "+f"(d[1]), "+f"(d[2]), "+f"(d[3])
                 : "r"(a[0]), "r"(a[1]), "r"(a[2]), "r"(a[3]), "r"(b[0]), "r"(b[1]));
}

__device__ __forceinline__ void cp_async16(uint32_t sa, const void* g, int sz) {
    asm volatile("cp.async.cg.shared.global [%0], [%1], 16, %2;"
                 :: "r"(sa), "l"(g), "r"(sz) : "memory");
}
__device__ __forceinline__ void cp_commit() {
    asm volatile("cp.async.commit_group;" ::: "memory");
}
__device__ __forceinline__ void cp_wait0() {
    asm volatile("cp.async.wait_group 0;" ::: "memory");
}

// ---------------- prep: weights->fp16, x->fp16, degree hist + ranks ---------
__global__ void k_prep(const int* __restrict__ dst, int E,
                       int* __restrict__ cnt, int* __restrict__ rank,
                       const float* __restrict__ x, __half* __restrict__ xh,
                       const float* __restrict__ Wl0, const float* __restrict__ Wr0,
                       const float* __restrict__ Wl1, const float* __restrict__ Wr1,
                       const float* __restrict__ Wl2, const float* __restrict__ Wr2,
                       __half* __restrict__ W) {
    int idx = blockIdx.x * blockDim.x + threadIdx.x;
    int stride = gridDim.x * blockDim.x;

    if (idx < WTOT) {
        const int T01 = 128 * 256;
        float v;
        if (idx < T01) {
            int n = idx >> 8, k = idx & 255;
            v = (k < 128) ? __ldg(Wl0 + k * 128 + n) : __ldg(Wr0 + (k - 128) * 128 + n);
        } else if (idx < 2 * T01) {
            int l = idx - T01;
            int n = l >> 8, k = l & 255;
            v = (k < 128) ? __ldg(Wl1 + k * 128 + n) : __ldg(Wr1 + (k - 128) * 128 + n);
        } else {
            int l = idx - 2 * T01;
            int n = l >> 7, k = l & 127;
            v = (n < 64) ? __ldg(Wl2 + k * 64 + n) : __ldg(Wr2 + k * 64 + (n - 64));
        }
        W[idx] = __float2half_rn(v);
    }

    const int X8 = N_NODES * D / 8;
    for (int i = idx; i < X8; i += stride) {
        float4 u0 = __ldg(reinterpret_cast<const float4*>(x) + i * 2);
        float4 u1 = __ldg(reinterpret_cast<const float4*>(x) + i * 2 + 1);
        __half2 h[4];
        h[0] = __float22half2_rn(make_float2(u0.x, u0.y));
        h[1] = __float22half2_rn(make_float2(u0.z, u0.w));
        h[2] = __float22half2_rn(make_float2(u1.x, u1.y));
        h[3] = __float22half2_rn(make_float2(u1.z, u1.w));
        reinterpret_cast<uint4*>(xh)[i] = *reinterpret_cast<uint4*>(h);
    }

    int nQ = E >> 2;
    for (int q = idx; q < nQ; q += stride) {
        int4 d = __ldg(reinterpret_cast<const int4*>(dst) + q);
        int4 r;
        r.x = atomicAdd(&cnt[d.x], 1);
        r.y = atomicAdd(&cnt[d.y], 1);
        r.z = atomicAdd(&cnt[d.z], 1);
        r.w = atomicAdd(&cnt[d.w], 1);
        *(reinterpret_cast<int4*>(rank) + q) = r;
    }
    for (int e = nQ * 4 + idx; e < E; e += stride)
        rank[e] = atomicAdd(&cnt[__ldg(dst + e)], 1);
}

// single block, 1024 threads: chunked warp-shuffle exclusive scan.
// Coalesced loads; self-zeroes cnt for next graph replay.
__global__ void k_scan(int* __restrict__ cnt, int* __restrict__ row_ptr) {
    __shared__ int warpsum[32];
    __shared__ int carry;
    const int t = threadIdx.x;
    const int lane = t & 31;
    const int wid = t >> 5;
    if (t == 0) carry = 0;
    __syncthreads();

    const int NCH = (N_NODES + 1023) / 1024;
    for (int ch = 0; ch < NCH; ch++) {
        int i = ch * 1024 + t;
        int v = 0;
        if (i < N_NODES) { v = cnt[i]; cnt[i] = 0; }
        int s = v;
#pragma unroll
        for (int o = 1; o < 32; o <<= 1) {
            int u = __shfl_up_sync(0xffffffffu, s, o);
            if (lane >= o) s += u;
        }
        if (lane == 31) warpsum[wid] = s;
        __syncthreads();
        if (wid == 0) {
            int ws = warpsum[lane];
#pragma unroll
            for (int o = 1; o < 32; o <<= 1) {
                int u = __shfl_up_sync(0xffffffffu, ws, o);
                if (lane >= o) ws += u;
            }
            warpsum[lane] = ws;
        }
        __syncthreads();
        int wbase = (wid > 0) ? warpsum[wid - 1] : 0;
        int base = carry;
        if (i < N_NODES) row_ptr[i] = base + wbase + s - v;
        __syncthreads();
        if (t == 0) carry += warpsum[31];
        __syncthreads();
    }
    if (t == 0) row_ptr[N_NODES] = carry;
}

// atomic-free fill using precomputed ranks
__global__ void k_fill(const int* __restrict__ src, const int* __restrict__ dst,
                       int E, const int* __restrict__ rank,
                       const int* __restrict__ row_ptr, int* __restrict__ csr) {
    int i = blockIdx.x * blockDim.x + threadIdx.x;
    int stride = gridDim.x * blockDim.x;
    int nQ = E >> 2;
    for (int q = i; q < nQ; q += stride) {
        int4 d = __ldg(reinterpret_cast<const int4*>(dst) + q);
        int4 s = __ldg(reinterpret_cast<const int4*>(src) + q);
        int4 r = __ldg(reinterpret_cast<const int4*>(rank) + q);
        csr[__ldg(row_ptr + d.x) + r.x] = s.x;
        csr[__ldg(row_ptr + d.y) + r.y] = s.y;
        csr[__ldg(row_ptr + d.z) + r.z] = s.z;
        csr[__ldg(row_ptr + d.w) + r.w] = s.w;
    }
    for (int e = nQ * 4 + i; e < E; e += stride)
        csr[__ldg(row_ptr + __ldg(dst + e)) + __ldg(rank + e)] = __ldg(src + e);
}

// ---------------- aggregation: half-warp per node, uint4 gather -------------
// 16 lanes x 8 halves per row; 2 nodes per warp -> 2x MLP, half the LDGs.
// Block 0 zeroes the given stats buffers.
__global__ __launch_bounds__(256)
void k_aggregate(const __half* __restrict__ xin, const int* __restrict__ csr,
                 const int* __restrict__ row_ptr, __half* __restrict__ M,
                 float* __restrict__ zSum, float* __restrict__ zSq) {
    int tid = threadIdx.x;
    if (blockIdx.x == 0 && tid < 128) { zSum[tid] = 0.f; zSq[tid] = 0.f; }

    int w = (blockIdx.x * blockDim.x + tid) >> 4;   // half-warp per node
    if (w >= N_NODES) return;
    int lane = tid & 15;

    int beg = __ldg(row_ptr + w);
    int end = __ldg(row_ptr + w + 1);
    float4 accA = make_float4(0.f, 0.f, 0.f, 0.f);
    float4 accB = make_float4(0.f, 0.f, 0.f, 0.f);

    int i = beg;
    for (; i + 1 < end; i += 2) {
        int s0 = __ldg(csr + i);
        int s1 = __ldg(csr + i + 1);
        uint4 u0 = __ldg(reinterpret_cast<const uint4*>(xin + (size_t)s0 * D) + lane);
        uint4 u1 = __ldg(reinterpret_cast<const uint4*>(xin + (size_t)s1 * D) + lane);
        __half2 p0 = __hadd2(*reinterpret_cast<__half2*>(&u0.x), *reinterpret_cast<__half2*>(&u1.x));
        __half2 p1 = __hadd2(*reinterpret_cast<__half2*>(&u0.y), *reinterpret_cast<__half2*>(&u1.y));
        __half2 p2 = __hadd2(*reinterpret_cast<__half2*>(&u0.z), *reinterpret_cast<__half2*>(&u1.z));
        __half2 p3 = __hadd2(*reinterpret_cast<__half2*>(&u0.w), *reinterpret_cast<__half2*>(&u1.w));
        float2 f0 = __half22float2(p0);
        float2 f1 = __half22float2(p1);
        float2 f2 = __half22float2(p2);
        float2 f3 = __half22float2(p3);
        accA.x += f0.x; accA.y += f0.y; accA.z += f1.x; accA.w += f1.y;
        accB.x += f2.x; accB.y += f2.y; accB.z += f3.x; accB.w += f3.y;
    }
    if (i < end) {
        int s0 = __ldg(csr + i);
        uint4 u0 = __ldg(reinterpret_cast<const uint4*>(xin + (size_t)s0 * D) + lane);
        float2 f0 = __half22float2(*reinterpret_cast<__half2*>(&u0.x));
        float2 f1 = __half22float2(*reinterpret_cast<__half2*>(&u0.y));
        float2 f2 = __half22float2(*reinterpret_cast<__half2*>(&u0.z));
        float2 f3 = __half22float2(*reinterpret_cast<__half2*>(&u0.w));
        accA.x += f0.x; accA.y += f0.y; accA.z += f1.x; accA.w += f1.y;
        accB.x += f2.x; accB.y += f2.y; accB.z += f3.x; accB.w += f3.y;
    }

    float inv = 1.f / (float)max(end - beg, 1);
    __half2 o[4];
    o[0] = __float22half2_rn(make_float2(accA.x * inv, accA.y * inv));
    o[1] = __float22half2_rn(make_float2(accA.z * inv, accA.w * inv));
    o[2] = __float22half2_rn(make_float2(accB.x * inv, accB.y * inv));
    o[3] = __float22half2_rn(make_float2(accB.z * inv, accB.w * inv));
    *reinterpret_cast<uint4*>(M + (size_t)w * D + lane * 8) = *reinterpret_cast<uint4*>(o);
}

// ---------------- BN+ReLU in place on fp16 h (layer 0 only) -----------------
__global__ __launch_bounds__(256)
void k_bn_apply(__half* __restrict__ h,
                const float* __restrict__ stSum, const float* __restrict__ stSq,
                const float* __restrict__ gamma, const float* __restrict__ beta) {
    __shared__ float ssc[128], ssh[128];
    int tid = threadIdx.x;
    if (tid < 128) {
        float mu = __ldg(stSum + tid) / (float)N_NODES;
        float var = __ldg(stSq + tid) / (float)N_NODES - mu * mu;
        float sc = __ldg(gamma + tid) * rsqrtf(var + BN_EPS);
        ssc[tid] = sc;
        ssh[tid] = __ldg(beta + tid) - mu * sc;
    }
    __syncthreads();

    const int T8 = N_NODES * D / 8;
    for (int i = blockIdx.x * blockDim.x + tid; i < T8; i += gridDim.x * blockDim.x) {
        int c8 = (i & 15) * 8;
        uint4 u = *(reinterpret_cast<uint4*>(h) + i);
        __half2* hp = reinterpret_cast<__half2*>(&u);
#pragma unroll
        for (int j = 0; j < 4; j++) {
            float2 f = __half22float2(hp[j]);
            f.x = fmaxf(fmaf(f.x, ssc[c8 + 2 * j], ssh[c8 + 2 * j]), 0.f);
            f.y = fmaxf(fmaf(f.y, ssc[c8 + 2 * j + 1], ssh[c8 + 2 * j + 1]), 0.f);
            hp[j] = __float22half2_rn(f);
        }
        *(reinterpret_cast<uint4*>(h) + i) = u;
    }
}

// ---------------- fp16 HMMA GEMM layers 0/1 (K=256, N=128), cp.async 2-buf --
__global__ __launch_bounds__(256)
void k_mma_gemm(const __half* __restrict__ M, const __half* __restrict__ selfSrc,
                const __half* __restrict__ W, const float* __restrict__ bias,
                __half* __restrict__ out,
                float* __restrict__ stOutSum, float* __restrict__ stOutSq) {
    constexpr int RS = 72;
    constexpr int NT = 8;
    constexpr int BUF = 128 * RS;
    extern __shared__ __half sm[];

    __shared__ float ssum[128];
    __shared__ float ssq[128];

    const int tid = threadIdx.x;
    const int lane = tid & 31;
    const int warp = tid >> 5;
    const int wr = warp & 3;
    const int wc = warp >> 2;
    const int rowBase = blockIdx.x * 128;

    if (tid < 128) { ssum[tid] = 0.f; ssq[tid] = 0.f; }

    float acc[2][NT][4];
#pragma unroll
    for (int mt = 0; mt < 2; mt++)
#pragma unroll
        for (int nt = 0; nt < NT; nt++)
#pragma unroll
            for (int j = 0; j < 4; j++) acc[mt][nt][j] = 0.f;

    auto issue = [&](int stage, int b) {
        const __half* Asrc = (stage < 2) ? M : selfSrc;
        const int colBase = (stage & 1) * 64;
        __half* sA = sm + b * 2 * BUF;
        __half* sW = sA + BUF;
#pragma unroll
        for (int t = 0; t < 4; t++) {
            int idx = tid + t * 256;
            int r = idx >> 3, c = idx & 7;
            int row = rowBase + r;
            int ok = (row < N_NODES) ? 16 : 0;
            int srow = (row < N_NODES) ? row : 0;
            cp_async16(smem_u32(sA + r * RS + c * 8),
                       Asrc + (size_t)srow * D + colBase + c * 8, ok);
        }
#pragma unroll
        for (int t = 0; t < 4; t++) {
            int idx = tid + t * 256;
            int n = idx >> 3, c = idx & 7;
            cp_async16(smem_u32(sW + n * RS + c * 8),
                       W + (size_t)n * 256 + stage * 64 + c * 8, 16);
        }
        cp_commit();
    };

    issue(0, 0);

    for (int stage = 0; stage < 4; stage++) {
        cp_wait0();
        __syncthreads();
        if (stage + 1 < 4) issue(stage + 1, (stage + 1) & 1);

        const uint32_t sbA = smem_u32(sm + (stage & 1) * 2 * BUF);
        const uint32_t sbW = sbA + BUF * 2;

#pragma unroll
        for (int ks = 0; ks < 4; ks++) {
            const uint32_t koff = (uint32_t)(ks * 16 + (lane >> 4) * 8) * 2;
            uint32_t a[2][4];
#pragma unroll
            for (int mt = 0; mt < 2; mt++) {
                uint32_t roff = (uint32_t)(wr * 32 + mt * 16 + (lane & 15)) * (RS * 2) + koff;
                ldsm4(a[mt], sbA + roff);
            }
            uint32_t b[NT][2];
#pragma unroll
            for (int g = 0; g < NT / 2; g++) {
                uint32_t roff = (uint32_t)(wc * 64 + g * 16 + (lane & 15)) * (RS * 2) + koff;
                uint32_t r[4];
                ldsm4(r, sbW + roff);
                b[2 * g][0] = r[0]; b[2 * g][1] = r[2];
                b[2 * g + 1][0] = r[1]; b[2 * g + 1][1] = r[3];
            }
#pragma unroll
            for (int mt = 0; mt < 2; mt++)
#pragma unroll
                for (int nt = 0; nt < NT; nt++)
                    mma16816f(acc[mt][nt], a[mt], b[nt]);
        }
        __syncthreads();
    }

#pragma unroll
    for (int nt = 0; nt < NT; nt++) {
        int col = wc * 64 + nt * 8 + (lane & 3) * 2;
        float2 bb = *reinterpret_cast<const float2*>(bias + col);
        float s0 = 0.f, s1 = 0.f, q0 = 0.f, q1 = 0.f;
#pragma unroll
        for (int mt = 0; mt < 2; mt++) {
            int r0 = rowBase + wr * 32 + mt * 16 + (lane >> 2);
            float v0 = acc[mt][nt][0] + bb.x, v1 = acc[mt][nt][1] + bb.y;
            float v2 = acc[mt][nt][2] + bb.x, v3 = acc[mt][nt][3] + bb.y;
            if (r0 < N_NODES) {
                *reinterpret_cast<__half2*>(out + (size_t)r0 * 128 + col) =
                    __float22half2_rn(make_float2(v0, v1));
                s0 += v0; s1 += v1; q0 += v0 * v0; q1 += v1 * v1;
            }
            if (r0 + 8 < N_NODES) {
                *reinterpret_cast<__half2*>(out + (size_t)(r0 + 8) * 128 + col) =
                    __float22half2_rn(make_float2(v2, v3));
                s0 += v2; s1 += v3; q0 += v2 * v2; q1 += v3 * v3;
            }
        }
#pragma unroll
        for (int off = 4; off < 32; off <<= 1) {
            s0 += __shfl_down_sync(0xffffffffu, s0, off);
            s1 += __shfl_down_sync(0xffffffffu, s1, off);
            q0 += __shfl_down_sync(0xffffffffu, q0, off);
            q1 += __shfl_down_sync(0xffffffffu, q1, off);
        }
        if ((lane >> 2) == 0) {
            atomicAdd(&ssum[col], s0); atomicAdd(&ssum[col + 1], s1);
            atomicAdd(&ssq[col], q0);  atomicAdd(&ssq[col + 1], q1);
        }
    }
    __syncthreads();
    if (tid < 128) {
        atomicAdd(&stOutSum[tid], ssum[tid]);
        atomicAdd(&stOutSq[tid], ssq[tid]);
    }
}

// ---------------- layer-2 GEMM: [z | s+b2] = relu(bn(h1)) @ [Wl2|Wr2]^T -----
__global__ __launch_bounds__(256)
void k_gemm_l2(const __half* __restrict__ hin,
               const float* __restrict__ stSum, const float* __restrict__ stSq,
               const float* __restrict__ gamma, const float* __restrict__ beta,
               const __half* __restrict__ W, const float* __restrict__ b2,
               __half* __restrict__ zout) {
    constexpr int RS = 72;
    constexpr int NT = 8;
    extern __shared__ __half sm[];
    __half* sA = sm;
    __half* sW = sm + 128 * RS;

    __shared__ float ssc[128], ssh[128];

    const int tid = threadIdx.x;
    const int lane = tid & 31;
    const int warp = tid >> 5;
    const int wr = warp & 3;
    const int wc = warp >> 2;
    const int rowBase = blockIdx.x * 128;

    if (tid < 128) {
        float mu = __ldg(stSum + tid) / (float)N_NODES;
        float var = __ldg(stSq + tid) / (float)N_NODES - mu * mu;
        float sc = __ldg(gamma + tid) * rsqrtf(var + BN_EPS);
        ssc[tid] = sc;
        ssh[tid] = __ldg(beta + tid) - mu * sc;
    }
    __syncthreads();

    const uint32_t sbA = smem_u32(sA);
    const uint32_t sbW = smem_u32(sW);

    float acc[2][NT][4];
#pragma unroll
    for (int mt = 0; mt < 2; mt++)
#pragma unroll
        for (int nt = 0; nt < NT; nt++)
#pragma unroll
            for (int j = 0; j < 4; j++) acc[mt][nt][j] = 0.f;

    for (int stage = 0; stage < 2; stage++) {
#pragma unroll
        for (int t = 0; t < 4; t++) {
            int idx = tid + t * 256;
            int r = idx >> 3, c = idx & 7;
            int row = rowBase + r;
            int col0 = stage * 64 + c * 8;
            uint4 u = make_uint4(0, 0, 0, 0);
            if (row < N_NODES) {
                u = __ldg(reinterpret_cast<const uint4*>(hin + (size_t)row * D + col0));
                __half2* hp = reinterpret_cast<__half2*>(&u);
#pragma unroll
                for (int j = 0; j < 4; j++) {
                    float2 f = __half22float2(hp[j]);
                    f.x = fmaxf(fmaf(f.x, ssc[col0 + 2 * j], ssh[col0 + 2 * j]), 0.f);
                    f.y = fmaxf(fmaf(f.y, ssc[col0 + 2 * j + 1], ssh[col0 + 2 * j + 1]), 0.f);
                    hp[j] = __float22half2_rn(f);
                }
            }
            *reinterpret_cast<uint4*>(sA + r * RS + c * 8) = u;
        }
#pragma unroll
        for (int t = 0; t < 4; t++) {
            int idx = tid + t * 256;
            int n = idx >> 3, c = idx & 7;
            uint4 v = __ldg(reinterpret_cast<const uint4*>(W + (size_t)n * 128 + stage * 64) + c);
            *reinterpret_cast<uint4*>(sW + n * RS + c * 8) = v;
        }
        __syncthreads();

#pragma unroll
        for (int ks = 0; ks < 4; ks++) {
            const uint32_t koff = (uint32_t)(ks * 16 + (lane >> 4) * 8) * 2;
            uint32_t a[2][4];
#pragma unroll
            for (int mt = 0; mt < 2; mt++) {
                uint32_t roff = (uint32_t)(wr * 32 + mt * 16 + (lane & 15)) * (RS * 2) + koff;
                ldsm4(a[mt], sbA + roff);
            }
            uint32_t b[NT][2];
#pragma unroll
            for (int g = 0; g < NT / 2; g++) {
                uint32_t roff = (uint32_t)(wc * 64 + g * 16 + (lane & 15)) * (RS * 2) + koff;
                uint32_t r[4];
                ldsm4(r, sbW + roff);
                b[2 * g][0] = r[0]; b[2 * g][1] = r[2];
                b[2 * g + 1][0] = r[1]; b[2 * g + 1][1] = r[3];
            }
#pragma unroll
            for (int mt = 0; mt < 2; mt++)
#pragma unroll
                for (int nt = 0; nt < NT; nt++)
                    mma16816f(acc[mt][nt], a[mt], b[nt]);
        }
        __syncthreads();
    }

#pragma unroll
    for (int nt = 0; nt < NT; nt++) {
        int col = wc * 64 + nt * 8 + (lane & 3) * 2;
        float2 bb = make_float2(0.f, 0.f);
        if (wc == 1) bb = *reinterpret_cast<const float2*>(b2 + (col - 64));
#pragma unroll
        for (int mt = 0; mt < 2; mt++) {
            int r0 = rowBase + wr * 32 + mt * 16 + (lane >> 2);
            if (r0 < N_NODES)
                *reinterpret_cast<__half2*>(zout + (size_t)r0 * 128 + col) =
                    __float22half2_rn(make_float2(acc[mt][nt][0] + bb.x, acc[mt][nt][1] + bb.y));
            if (r0 + 8 < N_NODES)
                *reinterpret_cast<__half2*>(zout + (size_t)(r0 + 8) * 128 + col) =
                    __float22half2_rn(make_float2(acc[mt][nt][2] + bb.x, acc[mt][nt][3] + bb.y));
        }
    }
}

// ---------------- final: out = log_softmax(mean(z[src]) + (s+b2)) -----------
__global__ __launch_bounds__(256)
void k_final(const __half* __restrict__ zs, const int* __restrict__ csr,
             const int* __restrict__ row_ptr, float* __restrict__ out) {
    int w = (blockIdx.x * blockDim.x + threadIdx.x) >> 5;
    if (w >= N_NODES) return;
    int lane = threadIdx.x & 31;
    int beg = __ldg(row_ptr + w);
    int end = __ldg(row_ptr + w + 1);
    float2 a = make_float2(0.f, 0.f);
    int i = beg;
    for (; i + 3 < end; i += 4) {
        int s0 = __ldg(csr + i);
        int s1 = __ldg(csr + i + 1);
        int s2 = __ldg(csr + i + 2);
        int s3 = __ldg(csr + i + 3);
        __half2 u0 = __ldg(reinterpret_cast<const __half2*>(zs + (size_t)s0 * 128) + lane);
        __half2 u1 = __ldg(reinterpret_cast<const __half2*>(zs + (size_t)s1 * 128) + lane);
        __half2 u2 = __ldg(reinterpret_cast<const __half2*>(zs + (size_t)s2 * 128) + lane);
        __half2 u3 = __ldg(reinterpret_cast<const __half2*>(zs + (size_t)s3 * 128) + lane);
        __half2 t = __hadd2(__hadd2(u0, u1), __hadd2(u2, u3));
        float2 f = __half22float2(t);
        a.x += f.x; a.y += f.y;
    }
    for (; i < end; i++) {
        int s0 = __ldg(csr + i);
        float2 f = __half22float2(__ldg(reinterpret_cast<const __half2*>(zs + (size_t)s0 * 128) + lane));
        a.x += f.x; a.y += f.y;
    }
    float inv = 1.f / (float)max(end - beg, 1);
    float2 sv = __half22float2(__ldg(reinterpret_cast<const __half2*>(zs + (size_t)w * 128 + 64) + lane));
    float v0 = a.x * inv + sv.x;
    float v1 = a.y * inv + sv.y;
    float m = fmaxf(v0, v1);
#pragma unroll
    for (int o = 16; o > 0; o >>= 1) m = fmaxf(m, __shfl_xor_sync(0xffffffffu, m, o));
    float e = expf(v0 - m) + expf(v1 - m);
#pragma unroll
    for (int o = 16; o > 0; o >>= 1) e += __shfl_xor_sync(0xffffffffu, e, o);
    float l = m + logf(e);
    *(reinterpret_cast<float2*>(out + (size_t)w * D_OUT) + lane) = make_float2(v0 - l, v1 - l);
}

// ---------------- launch ----------------------------------------------------
extern "C" void kernel_launch(void* const* d_in, const int* in_sizes, int n_in,
                              void* d_out, int out_size) {
    const float* x   = (const float*)d_in[0];
    const int* ei    = (const int*)d_in[1];
    const float* Wl0 = (const float*)d_in[2];
    const float* Wr0 = (const float*)d_in[3];
    const float* b0  = (const float*)d_in[4];
    const float* g0  = (const float*)d_in[5];
    const float* be0 = (const float*)d_in[6];
    const float* Wl1 = (const float*)d_in[7];
    const float* Wr1 = (const float*)d_in[8];
    const float* b1  = (const float*)d_in[9];
    const float* g1  = (const float*)d_in[10];
    const float* be1 = (const float*)d_in[11];
    const float* Wl2 = (const float*)d_in[12];
    const float* Wr2 = (const float*)d_in[13];
    const float* b2  = (const float*)d_in[14];
    float* out = (float*)d_out;

    const int E = in_sizes[1] / 2;
    const int* src = ei;
    const int* dst = ei + E;

    __half *xh, *M, *W, *h0, *h1;
    float *sum0, *sq0, *sum1, *sq1;
    int *cnti, *rowptr, *rank, *csr;
    cudaGetSymbolAddress((void**)&xh, g_xh);
    cudaGetSymbolAddress((void**)&M, g_M);
    cudaGetSymbolAddress((void**)&W, g_W);
    cudaGetSymbolAddress((void**)&h0, g_h0);
    cudaGetSymbolAddress((void**)&h1, g_h1);
    cudaGetSymbolAddress((void**)&cnti, g_cnti);
    cudaGetSymbolAddress((void**)&rowptr, g_rowptr);
    cudaGetSymbolAddress((void**)&rank, g_rank);
    cudaGetSymbolAddress((void**)&csr, g_csr);
    cudaGetSymbolAddress((void**)&sum0, g_sum0);
    cudaGetSymbolAddress((void**)&sq0, g_sq0);
    cudaGetSymbolAddress((void**)&sum1, g_sum1);
    cudaGetSymbolAddress((void**)&sq1, g_sq1);

    constexpr int RS = 72;
    const int SMEM  = 4 * 128 * RS * 2;  // 73728: 2 buffers x (A + W)
    const int SMEM2 = 2 * 128 * RS * 2;  // 36864: single buffer (gemm_l2)
    cudaFuncSetAttribute((const void*)k_mma_gemm, cudaFuncAttributeMaxDynamicSharedMemorySize, SMEM);
    cudaFuncSetAttribute((const void*)k_gemm_l2, cudaFuncAttributeMaxDynamicSharedMemorySize, SMEM2);

    const int aggBlocks  = (N_NODES * 16 + 255) / 256;   // half-warp per node
    const int finBlocks  = (N_NODES * 32 + 255) / 256;
    const int gemmBlocks = (N_NODES + 127) / 128;

    __half* W0 = W;
    __half* W1 = W + 128 * 256;
    __half* W2 = W + 256 * 256;

    // ---- prep: weights + x->fp16 + CSR (single stream) ----
    k_prep<<<1024, 256>>>(dst, E, cnti, rank, x, xh,
                          Wl0, Wr0, Wl1, Wr1, Wl2, Wr2, W);
    k_scan<<<1, 1024>>>(cnti, rowptr);
    k_fill<<<1024, 256>>>(src, dst, E, rank, rowptr, csr);

    // ---- layer 0 ----
    k_aggregate<<<aggBlocks, 256>>>(xh, csr, rowptr, M, sum0, sq0);
    k_mma_gemm<<<gemmBlocks, 256, SMEM>>>(M, xh, W0, b0, h0, sum0, sq0);
    k_bn_apply<<<1024, 256>>>(h0, sum0, sq0, g0, be0);

    // ---- layer 1 ----
    k_aggregate<<<aggBlocks, 256>>>(h0, csr, rowptr, M, sum1, sq1);
    k_mma_gemm<<<gemmBlocks, 256, SMEM>>>(M, h0, W1, b1, h1, sum1, sq1);

    // ---- layer 2 (BN1 fused into GEMM A-load; then fp16 gather + softmax) --
    k_gemm_l2<<<gemmBlocks, 256, SMEM2>>>(h1, sum1, sq1, g1, be1, W2, b2, h0);
    k_final<<<finBlocks, 256>>>(h0, csr, rowptr, out);
}